// round 1
// baseline (speedup 1.0000x reference)
#include <cuda_runtime.h>
#include <math.h>

// Problem constants
#define B_   2
#define C_   512
#define HW_  32768          // H*W = 128*256
#define K_   19
#define CT_  32             // channels per block tile
#define NCT_ (C_/CT_)       // 16 channel tiles
#define NCH_ 16             // pixel chunks
#define CHUNK_ (HW_/NCH_)   // 2048 pixels per chunk
#define TP_  128            // pixels per smem tile
#define THREADS_ 256

// Scratch (no cudaMalloc allowed): per-(b, ctile, chunk, tensor, c-in-tile, k) partial sums
__device__ float d_scratch[B_*NCT_*NCH_*2*CT_*K_];   // 2.49 MB
__device__ float d_cen[B_*2*C_*K_];                  // per-class channel sums (un-normalized centers)
__device__ float d_dots[B_*2*K_*K_];                 // Gram matrices

// ---------------------------------------------------------------------------
// Kernel 1: segment sums. Block = (b, channel-tile of 32, pixel-chunk of 2048).
// Stage [32ch x 128px] tiles of S and T in SMEM (pitch 129 -> conflict-free
// column reads), then each warp handles one pixel across 32 channels: the
// class label is warp-uniform, so a uniform switch routes 32 elements with
// one LDS + one FADD per tensor.
// ---------------------------------------------------------------------------
__global__ __launch_bounds__(THREADS_) void seg_sums_kernel(
    const float* __restrict__ S,
    const float* __restrict__ T,
    const int*   __restrict__ tgt)
{
    // 9728 floats = 38912 B: holds 2 tiles of 32x129 (8256 floats) during the
    // main loop, reused as an 8x1216 cross-warp reduction buffer afterwards.
    __shared__ __align__(16) float smem[9728];
    __shared__ int slbl[TP_];

    float (*sS)[129] = (float(*)[129])smem;
    float (*sT)[129] = (float(*)[129])(smem + CT_*129);

    int blk = blockIdx.x;
    int b   = blk / (NCT_*NCH_);
    int rem = blk - b*(NCT_*NCH_);
    int ct  = rem / NCH_;
    int ch  = rem - ct*NCH_;

    const float* Sb = S + (size_t)(b*C_ + ct*CT_) * HW_;
    const float* Tb = T + (size_t)(b*C_ + ct*CT_) * HW_;
    const int*   Lb = tgt + (size_t)b * HW_;
    int px0 = ch * CHUNK_;

    float aS[K_], aT[K_];
#pragma unroll
    for (int k = 0; k < K_; k++) { aS[k] = 0.f; aT[k] = 0.f; }

    int tid  = threadIdx.x;
    int lane = tid & 31;
    int warp = tid >> 5;

    for (int t = 0; t < CHUNK_/TP_; ++t) {   // 16 tiles per chunk
        int p0 = px0 + t*TP_;
        if (tid < TP_) slbl[tid] = Lb[p0 + tid];
#pragma unroll
        for (int i = tid; i < CT_*TP_; i += THREADS_) {
            int r  = i >> 7;          // channel row in tile
            int cp = i & (TP_ - 1);   // pixel col in tile
            sS[r][cp] = Sb[(size_t)r*HW_ + p0 + cp];
            sT[r][cp] = Tb[(size_t)r*HW_ + p0 + cp];
        }
        __syncthreads();

        // warp w handles pixels w, w+8, ... ; lane = channel within tile
        for (int p = warp; p < TP_; p += 8) {
            int   k  = slbl[p];           // uniform across the warp
            float vS = sS[lane][p];       // conflict-free (pitch 129)
            float vT = sT[lane][p];
            switch (k) {
                case  0: aS[ 0]+=vS; aT[ 0]+=vT; break;
                case  1: aS[ 1]+=vS; aT[ 1]+=vT; break;
                case  2: aS[ 2]+=vS; aT[ 2]+=vT; break;
                case  3: aS[ 3]+=vS; aT[ 3]+=vT; break;
                case  4: aS[ 4]+=vS; aT[ 4]+=vT; break;
                case  5: aS[ 5]+=vS; aT[ 5]+=vT; break;
                case  6: aS[ 6]+=vS; aT[ 6]+=vT; break;
                case  7: aS[ 7]+=vS; aT[ 7]+=vT; break;
                case  8: aS[ 8]+=vS; aT[ 8]+=vT; break;
                case  9: aS[ 9]+=vS; aT[ 9]+=vT; break;
                case 10: aS[10]+=vS; aT[10]+=vT; break;
                case 11: aS[11]+=vS; aT[11]+=vT; break;
                case 12: aS[12]+=vS; aT[12]+=vT; break;
                case 13: aS[13]+=vS; aT[13]+=vT; break;
                case 14: aS[14]+=vS; aT[14]+=vT; break;
                case 15: aS[15]+=vS; aT[15]+=vT; break;
                case 16: aS[16]+=vS; aT[16]+=vT; break;
                case 17: aS[17]+=vS; aT[17]+=vT; break;
                case 18: aS[18]+=vS; aT[18]+=vT; break;
                default: break;
            }
        }
        __syncthreads();
    }

    // Cross-warp reduction: 8 warps x 32 lanes x 38 accumulators, via smem reuse.
    float* red = smem;   // [8][1216]
#pragma unroll
    for (int k = 0; k < K_; k++) {
        red[warp*1216 + lane*38 + k]      = aS[k];
        red[warp*1216 + lane*38 + K_ + k] = aT[k];
    }
    __syncthreads();
    for (int pos = tid; pos < CT_*38; pos += THREADS_) {
        float s = 0.f;
#pragma unroll
        for (int w = 0; w < 8; w++) s += red[w*1216 + pos];
        int cc  = pos / 38;
        int idx = pos - cc*38;
        int tt  = idx / K_;
        int kk  = idx - tt*K_;
        d_scratch[((((size_t)(b*NCT_ + ct)*NCH_ + ch)*2 + tt)*CT_ + cc)*K_ + kk] = s;
    }
}

// ---------------------------------------------------------------------------
// Kernel 2: reduce the NCH_ chunk partials -> d_cen[b][t][c][k]
// ---------------------------------------------------------------------------
__global__ void reduce_chunks_kernel()
{
    int idx = blockIdx.x * blockDim.x + threadIdx.x;
    const int total = B_*2*C_*K_;
    if (idx >= total) return;
    int k = idx % K_; int r = idx / K_;
    int c = r % C_;   r /= C_;
    int t = r % 2;    int b = r / 2;
    int ct = c >> 5, cc = c & 31;
    float s = 0.f;
#pragma unroll
    for (int ch = 0; ch < NCH_; ch++)
        s += d_scratch[((((size_t)(b*NCT_ + ct)*NCH_ + ch)*2 + t)*CT_ + cc)*K_ + k];
    d_cen[((size_t)(b*2 + t)*C_ + c)*K_ + k] = s;
}

// ---------------------------------------------------------------------------
// Kernel 3: Gram matrices dots[b][t][i][j] = sum_c cen[c][i]*cen[c][j].
// Cosine is invariant to the per-class 1/count scaling, so raw sums suffice.
// Block = (b,t,i), 128 threads over channels.
// ---------------------------------------------------------------------------
__global__ void dots_kernel()
{
    int blk = blockIdx.x;
    int i   = blk % K_;
    int bt  = blk / K_;
    const float* cen = d_cen + (size_t)bt * C_ * K_;

    float d[K_];
#pragma unroll
    for (int j = 0; j < K_; j++) d[j] = 0.f;

    for (int c = threadIdx.x; c < C_; c += 128) {
        float vi = cen[c*K_ + i];
#pragma unroll
        for (int j = 0; j < K_; j++) d[j] += vi * cen[c*K_ + j];
    }

    __shared__ float rs[K_][128];
#pragma unroll
    for (int j = 0; j < K_; j++) rs[j][threadIdx.x] = d[j];
    __syncthreads();
    for (int s = 64; s > 0; s >>= 1) {
        if (threadIdx.x < s) {
#pragma unroll
            for (int j = 0; j < K_; j++)
                rs[j][threadIdx.x] += rs[j][threadIdx.x + s];
        }
        __syncthreads();
    }
    if (threadIdx.x < K_)
        d_dots[((size_t)bt*K_ + i)*K_ + threadIdx.x] = rs[threadIdx.x][0];
}

// ---------------------------------------------------------------------------
// Kernel 4: loss = mean over (b,i,j) of (pcsim_S - pcsim_T)^2
// pcsim = dots_ij / (max(sqrt(dots_ii),1e-8) * max(sqrt(dots_jj),1e-8))
// ---------------------------------------------------------------------------
__global__ void loss_kernel(float* __restrict__ out)
{
    __shared__ float red[1024];
    int tid = threadIdx.x;
    float v = 0.f;
    if (tid < B_*K_*K_) {
        int j = tid % K_; int r = tid / K_;
        int i = r % K_;   int b = r / K_;
        const float* dS = d_dots + (size_t)(b*2 + 0)*K_*K_;
        const float* dT = d_dots + (size_t)(b*2 + 1)*K_*K_;
        float nSi = fmaxf(sqrtf(dS[i*K_ + i]), 1e-8f);
        float nSj = fmaxf(sqrtf(dS[j*K_ + j]), 1e-8f);
        float pS  = dS[i*K_ + j] / (nSi * nSj);
        float nTi = fmaxf(sqrtf(dT[i*K_ + i]), 1e-8f);
        float nTj = fmaxf(sqrtf(dT[j*K_ + j]), 1e-8f);
        float pT  = dT[i*K_ + j] / (nTi * nTj);
        float df  = pS - pT;
        v = df * df;
    }
    red[tid] = v;
    __syncthreads();
    for (int s = 512; s > 0; s >>= 1) {
        if (tid < s) red[tid] += red[tid + s];
        __syncthreads();
    }
    if (tid == 0) out[0] = red[0] / (float)(B_*K_*K_);
}

// ---------------------------------------------------------------------------
extern "C" void kernel_launch(void* const* d_in, const int* in_sizes, int n_in,
                              void* d_out, int out_size)
{
    const float* S   = (const float*)d_in[0];   // preds_S [2,512,128,256] f32
    const float* T   = (const float*)d_in[1];   // preds_T [2,512,128,256] f32
    const int*   tgt = (const int*)  d_in[2];   // target  [2,1,128,256] i32
    float* out = (float*)d_out;                 // scalar f32

    seg_sums_kernel<<<B_*NCT_*NCH_, THREADS_>>>(S, T, tgt);
    reduce_chunks_kernel<<<(B_*2*C_*K_ + 255)/256, 256>>>();
    dots_kernel<<<B_*2*K_, 128>>>();
    loss_kernel<<<1, 1024>>>(out);
}

// round 3
// speedup vs baseline: 2.0446x; 2.0446x over previous
#include <cuda_runtime.h>
#include <math.h>

// Problem constants
#define B_   2
#define C_   512
#define HW_  32768          // H*W = 128*256
#define K_   19
#define GC_  8              // channels per block (1 per warp)
#define NCT_ (C_/GC_)       // 64 channel tiles
#define NCHUNK_ 4
#define PXC_ (HW_/NCHUNK_)  // 8192 pixels per chunk

// Scratch: per-(b,chunk,t,c,k) partial class sums (fully overwritten each call)
__device__ float d_scr[B_*NCHUNK_*2*C_*K_];   // 622 KB
__device__ float d_dots[B_*2*K_*K_];          // Gram matrices

// ---------------------------------------------------------------------------
// Kernel 1: segment sums, branch-free.
// lane = pixel, warp = channel. Each warp streams its channel row for BOTH
// tensors via float4 loads and scatters into private SMEM bins bins[k][lane]
// (float2 packs S,T). Bank index == lane -> conflict-free for any label.
// No atomics, no branches, no staging of the feature tiles.
// ---------------------------------------------------------------------------
__global__ __launch_bounds__(256) void seg_kernel(
    const float* __restrict__ S,
    const float* __restrict__ T,
    const int*   __restrict__ tgt)
{
    __shared__ float2 bins[GC_][K_*32];   // 8 warps x 19x32 float2 = 38.9 KB
    __shared__ float  outb[GC_][2][K_];

    int tid  = threadIdx.x;
    int lane = tid & 31;
    int warp = tid >> 5;

    int blk   = blockIdx.x;               // b*256 + ct*4 + chunk
    int chunk = blk & (NCHUNK_ - 1);
    int ct    = (blk >> 2) & (NCT_ - 1);
    int b     = blk >> 8;
    int c     = ct * GC_ + warp;

    const float4* Sp = (const float4*)(S + ((size_t)(b*C_ + c))*HW_ + chunk*PXC_);
    const float4* Tp = (const float4*)(T + ((size_t)(b*C_ + c))*HW_ + chunk*PXC_);
    const int4*   Lp = (const int4*)(tgt + (size_t)b*HW_ + chunk*PXC_);

    float2* bin = bins[warp];
    for (int i = lane; i < K_*32; i += 32) bin[i] = make_float2(0.f, 0.f);
    __syncwarp();

#pragma unroll 4
    for (int it = 0; it < PXC_/128; ++it) {   // 64 iters, 128 px per iter
        int idx = it*32 + lane;
        float4 s  = Sp[idx];
        float4 tv = Tp[idx];
        int4   l  = Lp[idx];
        float2 v;
        v = bin[l.x*32 + lane]; v.x += s.x; v.y += tv.x; bin[l.x*32 + lane] = v;
        v = bin[l.y*32 + lane]; v.x += s.y; v.y += tv.y; bin[l.y*32 + lane] = v;
        v = bin[l.z*32 + lane]; v.x += s.z; v.y += tv.z; bin[l.z*32 + lane] = v;
        v = bin[l.w*32 + lane]; v.x += s.w; v.y += tv.w; bin[l.w*32 + lane] = v;
    }
    __syncwarp();

    // Reduce 32 lanes per class; shuffle tree.
#pragma unroll
    for (int k = 0; k < K_; ++k) {
        float2 v = bin[k*32 + lane];
#pragma unroll
        for (int off = 16; off; off >>= 1) {
            v.x += __shfl_down_sync(0xffffffff, v.x, off);
            v.y += __shfl_down_sync(0xffffffff, v.y, off);
        }
        if (lane == 0) { outb[warp][0][k] = v.x; outb[warp][1][k] = v.y; }
    }
    __syncwarp();

    // 2*K_ = 38 outputs > 32 lanes: must loop (R2 bug: single guarded store
    // left t=1,k=13..18 unwritten).
    for (int i = lane; i < 2*K_; i += 32) {
        int t = i >= K_;
        int k = i - t*K_;
        d_scr[((size_t)((b*NCHUNK_ + chunk)*2 + t)*C_ + c)*K_ + k] = outb[warp][t][k];
    }
}

// ---------------------------------------------------------------------------
// Kernel 2: Gram matrices. One block per (b,t). Stage chunk-summed centers
// (raw class sums; cosine is scale-invariant so counts cancel) in SMEM,
// then compute all 19x19 dot products.
// ---------------------------------------------------------------------------
__global__ __launch_bounds__(256) void dots_kernel()
{
    __shared__ float cen[C_*K_];   // 9728 floats = 38.9 KB
    int bt = blockIdx.x;           // b*2 + t
    int b  = bt >> 1, t = bt & 1;

    for (int i = threadIdx.x; i < C_*K_; i += 256) {
        float s = 0.f;
#pragma unroll
        for (int ch = 0; ch < NCHUNK_; ++ch)
            s += d_scr[(size_t)((b*NCHUNK_ + ch)*2 + t)*C_*K_ + i];
        cen[i] = s;
    }
    __syncthreads();

    for (int p = threadIdx.x; p < K_*K_; p += 256) {
        int i = p / K_, j = p % K_;
        float acc = 0.f;
#pragma unroll 8
        for (int c = 0; c < C_; ++c)
            acc += cen[c*K_ + i] * cen[c*K_ + j];
        d_dots[(size_t)bt*K_*K_ + p] = acc;
    }
}

// ---------------------------------------------------------------------------
// Kernel 3: loss = mean over (b,i,j) of (pcsim_S - pcsim_T)^2
// ---------------------------------------------------------------------------
__global__ void loss_kernel(float* __restrict__ out)
{
    __shared__ float red[1024];
    int tid = threadIdx.x;
    float v = 0.f;
    if (tid < B_*K_*K_) {
        int j = tid % K_; int r = tid / K_;
        int i = r % K_;   int b = r / K_;
        const float* dS = d_dots + (size_t)(b*2 + 0)*K_*K_;
        const float* dT = d_dots + (size_t)(b*2 + 1)*K_*K_;
        float nSi = fmaxf(sqrtf(dS[i*K_ + i]), 1e-8f);
        float nSj = fmaxf(sqrtf(dS[j*K_ + j]), 1e-8f);
        float pS  = dS[i*K_ + j] / (nSi * nSj);
        float nTi = fmaxf(sqrtf(dT[i*K_ + i]), 1e-8f);
        float nTj = fmaxf(sqrtf(dT[j*K_ + j]), 1e-8f);
        float pT  = dT[i*K_ + j] / (nTi * nTj);
        float df  = pS - pT;
        v = df * df;
    }
    red[tid] = v;
    __syncthreads();
    for (int s = 512; s > 0; s >>= 1) {
        if (tid < s) red[tid] += red[tid + s];
        __syncthreads();
    }
    if (tid == 0) out[0] = red[0] / (float)(B_*K_*K_);
}

// ---------------------------------------------------------------------------
extern "C" void kernel_launch(void* const* d_in, const int* in_sizes, int n_in,
                              void* d_out, int out_size)
{
    const float* S   = (const float*)d_in[0];   // preds_S [2,512,128,256] f32
    const float* T   = (const float*)d_in[1];   // preds_T [2,512,128,256] f32
    const int*   tgt = (const int*)  d_in[2];   // target  [2,1,128,256] i32
    float* out = (float*)d_out;                 // scalar f32

    seg_kernel<<<B_*NCT_*NCHUNK_, 256>>>(S, T, tgt);   // 512 blocks
    dots_kernel<<<B_*2, 256>>>();
    loss_kernel<<<1, 1024>>>(out);
}